// round 1
// baseline (speedup 1.0000x reference)
#include <cuda_runtime.h>

#define PH 7
#define PW 7
#define SR 2
#define NS (PH*SR)        // 14 samples per axis
#define NB (PH*PW)        // 49 bins
#define TAPS (NB*16)      // 784 (bin * 4 samples * 4 corners)
#define TPB 128

__global__ __launch_bounds__(TPB) void roialign_kernel(
    const float* __restrict__ x, const float* __restrict__ rois,
    float* __restrict__ out, int C, int H, int W)
{
    __shared__ int   s_off[TAPS];
    __shared__ float s_w[TAPS];
    __shared__ int   s_il[2*NS];
    __shared__ int   s_ih[2*NS];
    __shared__ float s_w0[2*NS];
    __shared__ float s_w1[2*NS];
    __shared__ float s_out[TPB*NB];   // 128*49*4 = 25088 B

    const int k   = blockIdx.x;
    const int tid = threadIdx.x;

    const float r0  = rois[k*5+0];
    const float rx1 = rois[k*5+1];
    const float ry1 = rois[k*5+2];
    const float rx2 = rois[k*5+3];
    const float ry2 = rois[k*5+4];
    const int bidx  = (int)r0;

    // Per-axis sample tables (y: entries 0..13, x: entries 14..27), matching
    // the reference _axis() exactly (aligned=True, spatial_scale=0.25).
    if (tid < 2*NS) {
        int axis = tid / NS;            // 0 = y, 1 = x
        int n    = tid % NS;
        float limit = axis ? (float)W : (float)H;
        float start = (axis ? rx1 : ry1) * 0.25f - 0.5f;
        float end   = (axis ? rx2 : ry2) * 0.25f - 0.5f;
        float bin   = (end - start) * (1.0f / PH);
        int p = n >> 1, s = n & 1;
        float coord = start + ((float)p + ((float)s + 0.5f) * 0.5f) * bin;
        float valid = (coord >= -1.0f && coord <= limit) ? 1.0f : 0.0f;
        float c = fmaxf(coord, 0.0f);
        int low0 = (int)floorf(c);
        int lim  = (int)limit;
        bool cap = (low0 >= lim - 1);
        int low  = cap ? lim - 1 : low0;
        int high = cap ? lim - 1 : low0 + 1;
        if (cap) c = (float)low;
        float l = c - (float)low;
        float h = 1.0f - l;
        s_il[tid] = low;  s_ih[tid] = high;
        s_w0[tid] = h * valid;  s_w1[tid] = l * valid;
    }
    __syncthreads();

    // Build the flat 784-entry (offset, weight) tap table.
    for (int i = tid; i < TAPS; i += TPB) {
        int j   = i & 15;
        int bin = i >> 4;
        int ph = bin / PW, pw = bin % PW;
        int cx = j & 1, cy = (j >> 1) & 1, sx = (j >> 2) & 1, sy = (j >> 3) & 1;
        int ny = ph * SR + sy;
        int nx = pw * SR + sx;
        int   yi = cy ? s_ih[ny] : s_il[ny];
        float wy = cy ? s_w1[ny] : s_w0[ny];
        int   xi = cx ? s_ih[NS + nx] : s_il[NS + nx];
        float wx = cx ? s_w1[NS + nx] : s_w0[NS + nx];
        s_off[i] = yi * W + xi;
        s_w[i]   = wy * wx * 0.25f;    // fold the /(S*S) average in
    }
    __syncthreads();

    const long long plane = (long long)H * W;
    for (int r = 0; r < 2; r++) {
        int c = tid + r * TPB;
        const float* __restrict__ base = x + ((long long)bidx * C + c) * plane;
        for (int bin = 0; bin < NB; bin++) {
            float acc = 0.0f;
            #pragma unroll
            for (int t = 0; t < 16; t++) {
                int i = bin * 16 + t;
                acc = fmaf(s_w[i], __ldg(base + s_off[i]), acc);
            }
            s_out[tid * NB + bin] = acc;   // stride-49 words: conflict-free
        }
        __syncthreads();
        // Coalesced copy-out of this 128-channel chunk.
        float* o = out + ((long long)k * C + r * TPB) * NB;
        for (int i = tid; i < TPB * NB; i += TPB) o[i] = s_out[i];
        __syncthreads();
    }
}

extern "C" void kernel_launch(void* const* d_in, const int* in_sizes, int n_in,
                              void* d_out, int out_size)
{
    const float* x    = (const float*)d_in[0];
    const float* rois = (const float*)d_in[1];
    float* out        = (float*)d_out;
    const int K = in_sizes[1] / 5;
    // Shapes fixed by the problem: B=2, C=256, H=W=200.
    roialign_kernel<<<K, TPB>>>(x, rois, out, 256, 200, 200);
}

// round 2
// speedup vs baseline: 6.7257x; 6.7257x over previous
#include <cuda_runtime.h>

#define PHN 7
#define NSAMP 14          // PH * sampling_ratio
#define TPB 256
#define NWARP (TPB/32)

__global__ __launch_bounds__(TPB) void roialign_kernel(
    const float* __restrict__ x, const float* __restrict__ rois,
    float* __restrict__ out, int C, int H, int W)
{
    __shared__ int   s_yl[NSAMP], s_yh[NSAMP];     // pre-multiplied by W
    __shared__ float s_wy0[NSAMP], s_wy1[NSAMP];
    __shared__ int   s_xl[NSAMP], s_xh[NSAMP];
    __shared__ float s_wx0[NSAMP], s_wx1[NSAMP];
    __shared__ float s_stage[NWARP][49];
    __shared__ int   s_bidx;

    const int k    = blockIdx.x;
    const int tid  = threadIdx.x;
    const int lane = tid & 31;
    const int warp = tid >> 5;

    if (tid == 0) s_bidx = (int)rois[k*5];
    // Per-axis sample tables, matching reference _axis() exactly.
    if (tid < 2*NSAMP) {
        int axis = tid / NSAMP;            // 0 = y, 1 = x
        int n    = tid % NSAMP;
        float limit = axis ? (float)W : (float)H;
        float start = rois[k*5 + (axis ? 1 : 2)] * 0.25f - 0.5f;
        float end   = rois[k*5 + (axis ? 3 : 4)] * 0.25f - 0.5f;
        float bin   = (end - start) * (1.0f/7.0f);
        int p = n >> 1, s = n & 1;
        float coord = start + ((float)p + ((float)s + 0.5f) * 0.5f) * bin;
        float valid = (coord >= -1.0f && coord <= limit) ? 1.0f : 0.0f;
        float c = fmaxf(coord, 0.0f);
        int low0 = (int)floorf(c);
        int lim  = (int)limit;
        bool cap = (low0 >= lim - 1);
        int low  = cap ? lim - 1 : low0;
        int high = cap ? lim - 1 : low0 + 1;
        if (cap) c = (float)low;
        float l = c - (float)low;
        float h = 1.0f - l;
        if (axis) { s_xl[n] = low;     s_xh[n] = high;     s_wx0[n] = h*valid; s_wx1[n] = l*valid; }
        else      { s_yl[n] = low * W; s_yh[n] = high * W; s_wy0[n] = h*valid; s_wy1[n] = l*valid; }
    }
    __syncthreads();

    // Lane-resident x tap: lane l<28 -> sample l>>1, corner l&1.
    const int ll   = (lane < 28) ? lane : 27;
    const int nx   = ll >> 1;
    const int xoff = (ll & 1) ? s_xh[nx] : s_xl[nx];
    const float wx = (lane < 28)
                   ? (((lane & 1) ? s_wx1[nx] : s_wx0[nx]) * 0.25f)
                   : 0.0f;

    const long long plane = (long long)H * W;
    const float* __restrict__ xb = x + (long long)s_bidx * C * plane;

    for (int c = warp; c < C; c += NWARP) {
        const float* __restrict__ base = xb + (long long)c * plane + xoff;
        #pragma unroll
        for (int ph = 0; ph < PHN; ph++) {
            float acc = 0.0f;
            #pragma unroll
            for (int j = 0; j < 4; j++) {
                int ny     = 2*ph + (j >> 1);
                int   yoff = (j & 1) ? s_yh[ny]  : s_yl[ny];
                float wy   = (j & 1) ? s_wy1[ny] : s_wy0[ny];
                acc = fmaf(wy, __ldg(base + yoff), acc);
            }
            acc *= wx;
            // Reduce groups of 4 lanes (= one bin column pw).
            acc += __shfl_xor_sync(0xffffffffu, acc, 1);
            acc += __shfl_xor_sync(0xffffffffu, acc, 2);
            if (lane < 28 && (lane & 3) == 0)
                s_stage[warp][ph * 7 + (lane >> 2)] = acc;
        }
        __syncwarp();
        float* o = out + ((long long)k * C + c) * 49;
        for (int i = lane; i < 49; i += 32) o[i] = s_stage[warp][i];
        __syncwarp();
    }
}

extern "C" void kernel_launch(void* const* d_in, const int* in_sizes, int n_in,
                              void* d_out, int out_size)
{
    const float* x    = (const float*)d_in[0];
    const float* rois = (const float*)d_in[1];
    float* out        = (float*)d_out;
    const int K = in_sizes[1] / 5;
    roialign_kernel<<<K, TPB>>>(x, rois, out, 256, 200, 200);
}

// round 3
// speedup vs baseline: 9.5383x; 1.4182x over previous
#include <cuda_runtime.h>

#define PHN 7
#define NSAMP 14          // PH * sampling_ratio
#define TPB 256
#define NWARP (TPB/32)
#define CPW 2             // channels per warp iteration

__global__ __launch_bounds__(TPB) void roialign_kernel(
    const float* __restrict__ x, const float* __restrict__ rois,
    float* __restrict__ out, int C, int H, int W)
{
    __shared__ int   s_yl[NSAMP], s_yh[NSAMP];     // pre-multiplied by W
    __shared__ float s_wy0[NSAMP], s_wy1[NSAMP];
    __shared__ int   s_xl[NSAMP], s_xh[NSAMP];
    __shared__ float s_wx0[NSAMP], s_wx1[NSAMP];
    __shared__ int   s_bidx;

    const int k    = blockIdx.x;
    const int tid  = threadIdx.x;
    const int lane = tid & 31;
    const int warp = tid >> 5;

    if (tid == 0) s_bidx = (int)rois[k*5];
    // Per-axis sample tables, matching reference _axis() exactly.
    if (tid < 2*NSAMP) {
        int axis = tid / NSAMP;            // 0 = y, 1 = x
        int n    = tid % NSAMP;
        float limit = axis ? (float)W : (float)H;
        float start = rois[k*5 + (axis ? 1 : 2)] * 0.25f - 0.5f;
        float end   = rois[k*5 + (axis ? 3 : 4)] * 0.25f - 0.5f;
        float bin   = (end - start) * (1.0f/7.0f);
        int p = n >> 1, s = n & 1;
        float coord = start + ((float)p + ((float)s + 0.5f) * 0.5f) * bin;
        float valid = (coord >= -1.0f && coord <= limit) ? 1.0f : 0.0f;
        float c = fmaxf(coord, 0.0f);
        int low0 = (int)floorf(c);
        int lim  = (int)limit;
        bool cap = (low0 >= lim - 1);
        int low  = cap ? lim - 1 : low0;
        int high = cap ? lim - 1 : low0 + 1;
        if (cap) c = (float)low;
        float l = c - (float)low;
        float h = 1.0f - l;
        if (axis) { s_xl[n] = low;     s_xh[n] = high;     s_wx0[n] = h*valid; s_wx1[n] = l*valid; }
        else      { s_yl[n] = low * W; s_yh[n] = high * W; s_wy0[n] = h*valid; s_wy1[n] = l*valid; }
    }
    __syncthreads();

    // Lane-resident x tap: lane l<28 -> sample l>>1, corner l&1.
    const int ll   = (lane < 28) ? lane : 27;
    const int nx   = ll >> 1;
    const int xoff = (ll & 1) ? s_xh[nx] : s_xl[nx];
    const float wx = (lane < 28)
                   ? (((lane & 1) ? s_wx1[nx] : s_wx0[nx]) * 0.25f)
                   : 0.0f;

    // After the 4-lane bin reduction, lanes 0,4,..,24 hold pw=0..6; their
    // output addresses are contiguous floats -> single-wavefront STG.
    const bool wlane = (lane < 28) && ((lane & 3) == 0);
    const int  pw    = lane >> 2;

    const long long plane = (long long)H * W;
    const float* __restrict__ xb = x + (long long)s_bidx * C * plane;

    for (int c0 = warp * CPW; c0 < C; c0 += NWARP * CPW) {
        const float* __restrict__ base0 = xb + (long long)(c0 + 0) * plane + xoff;
        const float* __restrict__ base1 = xb + (long long)(c0 + 1) * plane + xoff;
        float* o0 = out + ((long long)k * C + c0 + 0) * 49 + pw;
        float* o1 = out + ((long long)k * C + c0 + 1) * 49 + pw;
        #pragma unroll
        for (int ph = 0; ph < PHN; ph++) {
            float a0 = 0.0f, a1 = 0.0f;
            #pragma unroll
            for (int j = 0; j < 4; j++) {
                int ny     = 2*ph + (j >> 1);
                int   yoff = (j & 1) ? s_yh[ny]  : s_yl[ny];
                float wy   = (j & 1) ? s_wy1[ny] : s_wy0[ny];
                float v0 = __ldg(base0 + yoff);
                float v1 = __ldg(base1 + yoff);
                a0 = fmaf(wy, v0, a0);
                a1 = fmaf(wy, v1, a1);
            }
            a0 *= wx;  a1 *= wx;
            a0 += __shfl_xor_sync(0xffffffffu, a0, 1);
            a1 += __shfl_xor_sync(0xffffffffu, a1, 1);
            a0 += __shfl_xor_sync(0xffffffffu, a0, 2);
            a1 += __shfl_xor_sync(0xffffffffu, a1, 2);
            if (wlane) {
                o0[ph * 7] = a0;
                o1[ph * 7] = a1;
            }
        }
    }
}

extern "C" void kernel_launch(void* const* d_in, const int* in_sizes, int n_in,
                              void* d_out, int out_size)
{
    const float* x    = (const float*)d_in[0];
    const float* rois = (const float*)d_in[1];
    float* out        = (float*)d_out;
    const int K = in_sizes[1] / 5;
    roialign_kernel<<<K, TPB>>>(x, rois, out, 256, 200, 200);
}